// round 1
// baseline (speedup 1.0000x reference)
#include <cuda_runtime.h>

#define D          200
#define REL_TOTAL  1000
#define BATCH      16384
#define MARGIN     4.0f

#define IPP   20            // items per pass
#define NPAIR 80            // IPP*4 entity vectors per pass
#define NP    8             // pairs per thread (pair-group size)
#define CGRP  50            // column groups (200/4)
#define PGS   10            // pair groups
#define MAIN_THREADS 512    // 500 active in matvec (50*10)

// floats: M 40000 + X 16000 + R 200 + NI 80 + Sc 40 + rinv 4
#define SMEM_FLOATS (40000 + 16000 + 200 + 80 + 40 + 4)
#define SMEM_BYTES  (SMEM_FLOATS * 4)

// ---- device scratch (no allocation allowed) ----
__device__ int    g_count[REL_TOTAL];
__device__ int    g_offset[REL_TOTAL + 1];
__device__ int    g_cursor[REL_TOTAL];
__device__ int    g_perm[BATCH];
__device__ double g_loss;

__device__ __forceinline__ void fma2(unsigned long long& d,
                                     unsigned long long a,
                                     unsigned long long b) {
    asm("fma.rn.f32x2 %0, %1, %2, %0;" : "+l"(d) : "l"(a), "l"(b));
}

__global__ void k_zero() {
    int t = blockIdx.x * blockDim.x + threadIdx.x;
    if (t < REL_TOTAL) g_count[t] = 0;
    if (t == 0) g_loss = 0.0;
}

__global__ void k_hist(const int* __restrict__ pos_r) {
    int i = blockIdx.x * blockDim.x + threadIdx.x;
    if (i < BATCH) atomicAdd(&g_count[pos_r[i]], 1);
}

__global__ void k_scan() {
    __shared__ int s[1024];
    int t = threadIdx.x;
    int c = (t < REL_TOTAL) ? g_count[t] : 0;
    s[t] = c;
    __syncthreads();
    for (int off = 1; off < 1024; off <<= 1) {
        int v = (t >= off) ? s[t - off] : 0;
        __syncthreads();
        s[t] += v;
        __syncthreads();
    }
    if (t < REL_TOTAL) {
        int ex = s[t] - c;           // exclusive prefix
        g_offset[t] = ex;
        g_cursor[t] = ex;
        if (t == REL_TOTAL - 1) g_offset[REL_TOTAL] = s[t];
    }
}

__global__ void k_scatter(const int* __restrict__ pos_r) {
    int i = blockIdx.x * blockDim.x + threadIdx.x;
    if (i < BATCH) {
        int p = atomicAdd(&g_cursor[pos_r[i]], 1);
        g_perm[p] = i;
    }
}

extern __shared__ float smem[];

__global__ void __launch_bounds__(MAIN_THREADS, 1)
k_main(const int* __restrict__ pos_h, const int* __restrict__ pos_t,
       const int* __restrict__ neg_h, const int* __restrict__ neg_t,
       const float* __restrict__ ent, const float* __restrict__ rel,
       const float* __restrict__ transfer)
{
    float* sM   = smem;                 // [200][200], row e contiguous in j
    float* sX   = sM + 40000;           // [80][200] entity vectors, reused as results
    float* sR   = sX + 16000;           // raw relation embedding
    float* sNI  = sR + D;               // 80 inverse norms
    float* sSc  = sNI + NPAIR;          // 40 scores
    float* sRi  = sSc + 40;             // rsqrt of relation norm

    const int r     = blockIdx.x;
    const int begin = g_offset[r];
    const int n     = g_offset[r + 1] - begin;
    if (n == 0) return;

    const int t    = threadIdx.x;
    const int lane = t & 31;
    const int warp = t >> 5;

    // ---- load relation matrix (160 KB) + relation embedding into SMEM ----
    {
        const float4* src = (const float4*)(transfer + (size_t)r * 40000);
        float4* dst = (float4*)sM;
        #pragma unroll 4
        for (int i = t; i < 10000; i += MAIN_THREADS) dst[i] = src[i];
    }
    if (t < D) sR[t] = rel[r * D + t];
    __syncthreads();

    if (warp == 0) {
        float ss = 0.f;
        #pragma unroll
        for (int c = 0; c < 7; c++) {
            int j = lane + 32 * c;
            if (j < D) { float v = sR[j]; ss += v * v; }
        }
        #pragma unroll
        for (int o = 16; o; o >>= 1) ss += __shfl_xor_sync(0xffffffffu, ss, o);
        if (lane == 0) *sRi = rsqrtf(fmaxf(ss, 1e-12f));
    }

    const bool active = (t < CGRP * PGS);
    const int  ct = active ? (t % CGRP) : 0;
    const int  pg = active ? (t / CGRP) : 0;

    double cta_sum = 0.0;

    for (int base = 0; base < n; base += IPP) {
        const int cnt = min(IPP, n - base);

        // ---- gather 80 entity vectors (zero-pad missing items) ----
        for (int q = 0; q < 5; q++) {
            int pair = warp * 5 + q;
            int it   = pair >> 2;
            int kind = pair & 3;
            float* dstv = sX + pair * D;
            if (it < cnt) {
                int bi  = g_perm[begin + base + it];
                int row = (kind == 0) ? pos_h[bi] : (kind == 1) ? pos_t[bi]
                        : (kind == 2) ? neg_h[bi] : neg_t[bi];
                const float* srcv = ent + (size_t)row * D;
                #pragma unroll
                for (int c = 0; c < 7; c++) {
                    int j = lane + 32 * c;
                    if (j < D) dstv[j] = srcv[j];
                }
            } else {
                #pragma unroll
                for (int c = 0; c < 7; c++) {
                    int j = lane + 32 * c;
                    if (j < D) dstv[j] = 0.f;
                }
            }
        }
        __syncthreads();

        // ---- main matvec: thread owns 4 columns x 8 pairs, full K=200 ----
        unsigned long long acc[NP][2];
        #pragma unroll
        for (int p = 0; p < NP; p++) { acc[p][0] = 0ull; acc[p][1] = 0ull; }

        if (active) {
            const float* xbase = sX + (pg * NP) * D;
            const float* mptr  = sM + 4 * ct;
            #pragma unroll 2
            for (int e = 0; e < D; e++) {
                ulonglong2 m = *(const ulonglong2*)mptr;   // LDS.128: 4 M columns
                mptr += D;
                #pragma unroll
                for (int p = 0; p < NP; p++) {
                    unsigned int xu = __float_as_uint(xbase[p * D + e]);
                    unsigned long long xx;
                    asm("mov.b64 %0, {%1, %1};" : "=l"(xx) : "r"(xu));
                    fma2(acc[p][0], xx, m.x);
                    fma2(acc[p][1], xx, m.y);
                }
            }
        }
        __syncthreads();   // everyone done reading sX

        if (active) {
            #pragma unroll
            for (int p = 0; p < NP; p++) {
                ulonglong2 v; v.x = acc[p][0]; v.y = acc[p][1];
                *(ulonglong2*)(sX + (pg * NP + p) * D + 4 * ct) = v;  // results overwrite sX
            }
        }
        __syncthreads();

        // ---- inverse L2 norms of all 80 projected vectors ----
        for (int q = 0; q < 5; q++) {
            int pair = warp * 5 + q;
            const float* v = sX + pair * D;
            float ss = 0.f;
            #pragma unroll
            for (int c = 0; c < 7; c++) {
                int j = lane + 32 * c;
                if (j < D) { float x = v[j]; ss += x * x; }
            }
            #pragma unroll
            for (int o = 16; o; o >>= 1) ss += __shfl_xor_sync(0xffffffffu, ss, o);
            if (lane == 0) sNI[pair] = rsqrtf(fmaxf(ss, 1e-12f));
        }
        __syncthreads();

        // ---- scores: 40 tasks = 20 items x {pos, neg} ----
        {
            float rinv = *sRi;
            for (int task = warp; task < 40; task += 16) {
                int it = task >> 1, s = task & 1;
                int hp = it * 4 + 2 * s, tp = hp + 1;
                float ih = sNI[hp], iT = sNI[tp];
                const float* vh = sX + hp * D;
                const float* vt = sX + tp * D;
                float sc = 0.f;
                #pragma unroll
                for (int c = 0; c < 7; c++) {
                    int j = lane + 32 * c;
                    if (j < D) sc += fabsf(vh[j] * ih + sR[j] * rinv - vt[j] * iT);
                }
                #pragma unroll
                for (int o = 16; o; o >>= 1) sc += __shfl_xor_sync(0xffffffffu, sc, o);
                if (lane == 0) sSc[task] = sc;
            }
        }
        __syncthreads();

        if (t == 0) {
            for (int it = 0; it < cnt; it++) {
                float v = sSc[2 * it] - sSc[2 * it + 1] + MARGIN;
                if (v > 0.f) cta_sum += (double)v;
            }
        }
        __syncthreads();   // protect sX/sSc before next pass
    }

    if (t == 0) atomicAdd(&g_loss, cta_sum);
}

__global__ void k_final(float* out) {
    out[0] = (float)(g_loss / (double)BATCH);
}

extern "C" void kernel_launch(void* const* d_in, const int* in_sizes, int n_in,
                              void* d_out, int out_size) {
    const int*   pos_h    = (const int*)d_in[0];
    const int*   pos_t    = (const int*)d_in[1];
    const int*   pos_r    = (const int*)d_in[2];
    const int*   neg_h    = (const int*)d_in[3];
    const int*   neg_t    = (const int*)d_in[4];
    const float* ent      = (const float*)d_in[5];
    const float* rel      = (const float*)d_in[6];
    const float* transfer = (const float*)d_in[7];
    float* out = (float*)d_out;

    cudaFuncSetAttribute(k_main, cudaFuncAttributeMaxDynamicSharedMemorySize, SMEM_BYTES);

    k_zero<<<1, 1024>>>();
    k_hist<<<(BATCH + 255) / 256, 256>>>(pos_r);
    k_scan<<<1, 1024>>>();
    k_scatter<<<(BATCH + 255) / 256, 256>>>(pos_r);
    k_main<<<REL_TOTAL, MAIN_THREADS, SMEM_BYTES>>>(pos_h, pos_t, neg_h, neg_t,
                                                    ent, rel, transfer);
    k_final<<<1, 1>>>(out);
}

// round 2
// speedup vs baseline: 1.5513x; 1.5513x over previous
#include <cuda_runtime.h>

#define D          200
#define REL_TOTAL  1000
#define BATCH      16384
#define MARGIN     4.0f

#define IPP        20          // items per pass
#define CGRP       50          // column groups (200/4)
#define NP         8           // pairs per thread
#define THREADS    512
#define GRID_MAIN  152

// floats: Mt 40000 + X 16000 + R 200 + NI 80 + Sc 40 + misc 8
#define SMEM_FLOATS (40000 + 16000 + 200 + 80 + 40 + 8)
#define SMEM_BYTES  (SMEM_FLOATS * 4)

typedef unsigned long long ull;

__device__ int    g_qhead;
__device__ int    g_offset[REL_TOTAL + 1];
__device__ int    g_perm[BATCH];
__device__ double g_part[REL_TOTAL];

__device__ __forceinline__ void fma2(ull& d, ull a, ull b) {
    asm("fma.rn.f32x2 %0, %1, %2, %0;" : "+l"(d) : "l"(a), "l"(b));
}

// ---------------- prep: hist + scan + scatter in one CTA ----------------
__global__ void k_prep(const int* __restrict__ pos_r) {
    __shared__ int h[1024];
    __shared__ int cur[REL_TOTAL];
    int t = threadIdx.x;
    h[t] = 0;
    if (t == 0) g_qhead = 0;
    __syncthreads();
    for (int i = t; i < BATCH; i += 1024) atomicAdd(&h[pos_r[i]], 1);
    __syncthreads();
    int c = h[t];
    for (int off = 1; off < 1024; off <<= 1) {
        int v = (t >= off) ? h[t - off] : 0;
        __syncthreads();
        h[t] += v;
        __syncthreads();
    }
    if (t < REL_TOTAL) {
        int ex = h[t] - c;
        g_offset[t] = ex;
        cur[t] = ex;
        if (t == REL_TOTAL - 1) g_offset[REL_TOTAL] = h[t];
    }
    __syncthreads();
    for (int i = t; i < BATCH; i += 1024) {
        int p = atomicAdd(&cur[pos_r[i]], 1);
        g_perm[p] = i;
    }
}

// ---------------- main persistent kernel ----------------
extern __shared__ float smem[];

__global__ void __launch_bounds__(THREADS, 1)
k_main(const int* __restrict__ pos_h, const int* __restrict__ pos_t,
       const int* __restrict__ neg_h, const int* __restrict__ neg_t,
       const float* __restrict__ ent, const float* __restrict__ rel,
       const float* __restrict__ transfer)
{
    float* sMt = smem;            // [200 rows j][200 e], rotation-swizzled granules
    float* sX  = sMt + 40000;     // [80][200]
    float* sR  = sX + 16000;      // 200
    float* sNI = sR + D;          // 80
    float* sSc = sNI + 80;        // 40
    float* sRi = sSc + 40;        // 1 (+pad)
    int*   sRel = (int*)(sRi + 4);

    const int t    = threadIdx.x;
    const int lane = t & 31;
    const int warp = t >> 5;
    const int ct   = t % CGRP;    // 0..49 for t<500
    const int pg   = t / CGRP;

    for (;;) {
        if (t == 0) *sRel = atomicAdd(&g_qhead, 1);
        __syncthreads();
        const int r = *sRel;
        if (r >= REL_TOTAL) break;

        const int begin = g_offset[r];
        const int n     = g_offset[r + 1] - begin;
        if (n == 0) {
            if (t == 0) g_part[r] = 0.0;
            continue;
        }

        // ---- load + transpose M into sMt with per-row granule rotation ----
        // element M[e][j] (j = 4*jg + c) stored at float index:
        //   (4*jg+c)*200 + slot*4 + (e&3),  slot = (e/4 + jg) mod 50
        {
            const float4* src = (const float4*)(transfer + (size_t)r * 40000);
            for (int idx = t; idx < 10000; idx += THREADS) {
                float4 v = src[idx];
                int e  = idx / 50;
                int jg = idx % 50;
                int slot = (e >> 2) + jg; if (slot >= 50) slot -= 50;
                int b = (4 * jg) * 200 + (slot << 2) + (e & 3);
                sMt[b      ] = v.x;
                sMt[b + 200] = v.y;
                sMt[b + 400] = v.z;
                sMt[b + 600] = v.w;
            }
            if (t < D) sR[t] = rel[r * D + t];
        }
        __syncthreads();

        if (warp == 0) {
            const float4* r4 = (const float4*)sR;
            float4 a = r4[lane];
            float ss = a.x * a.x + a.y * a.y + a.z * a.z + a.w * a.w;
            if (lane < 18) {
                float4 b = r4[lane + 32];
                ss += b.x * b.x + b.y * b.y + b.z * b.z + b.w * b.w;
            }
            #pragma unroll
            for (int o = 16; o; o >>= 1) ss += __shfl_xor_sync(0xffffffffu, ss, o);
            if (lane == 0) *sRi = rsqrtf(fmaxf(ss, 1e-12f));
        }

        double csum = 0.0;

        for (int base = 0; base < n; base += IPP) {
            const int cnt    = min(IPP, n - base);
            const int apairs = 4 * cnt;
            const int padTo  = (apairs + 7) & ~7;
            __syncthreads();   // prior pass readers done; Mt/sRi ready on first pass

            // ---- gather (pairs < apairs) / zero-pad (apairs..padTo) ----
            #pragma unroll
            for (int q = 0; q < 5; q++) {
                int pair = warp * 5 + q;
                if (pair >= padTo) continue;
                float4* dst = (float4*)(sX + pair * D);
                if (pair < apairs) {
                    int it = pair >> 2, kind = pair & 3;
                    int bi = g_perm[begin + base + it];
                    int row = (kind == 0) ? pos_h[bi] : (kind == 1) ? pos_t[bi]
                            : (kind == 2) ? neg_h[bi] : neg_t[bi];
                    const float4* srcv = (const float4*)(ent + (size_t)row * D);
                    dst[lane] = srcv[lane];
                    if (lane < 18) dst[lane + 32] = srcv[lane + 32];
                } else {
                    float4 z = make_float4(0.f, 0.f, 0.f, 0.f);
                    dst[lane] = z;
                    if (lane < 18) dst[lane + 32] = z;
                }
            }
            __syncthreads();

            // ---- matvec: thread owns cols 4ct..4ct+3 x pairs 8pg..8pg+7 ----
            // even/odd-e f32x2 accumulators: no duplication MOVs, pure LDS.128 + FMA2
            ull acc[NP][4];
            const bool act = (t < CGRP * 10) && (pg * NP < apairs);
            if (act) {
                #pragma unroll
                for (int p = 0; p < NP; p++)
                    #pragma unroll
                    for (int c = 0; c < 4; c++) acc[p][c] = 0ull;

                const float* xp = sX + pg * NP * D;
                const float* mb = sMt + 4 * ct * 200;
                int gr = ct;                      // rotated granule cursor
                #pragma unroll 2
                for (int eb = 0; eb < 50; ++eb) {
                    const float4* mp = (const float4*)(mb + (gr << 2));
                    float4 m0 = mp[0];            // col 4ct+0, e=4eb..4eb+3
                    float4 m1 = mp[50];
                    float4 m2 = mp[100];
                    float4 m3 = mp[150];
                    ull m0a = ((ull*)&m0)[0], m0b = ((ull*)&m0)[1];
                    ull m1a = ((ull*)&m1)[0], m1b = ((ull*)&m1)[1];
                    ull m2a = ((ull*)&m2)[0], m2b = ((ull*)&m2)[1];
                    ull m3a = ((ull*)&m3)[0], m3b = ((ull*)&m3)[1];
                    const float4* x4 = (const float4*)xp + eb;
                    #pragma unroll
                    for (int p = 0; p < NP; p++) {
                        float4 xv = x4[p * 50];
                        ull xa = ((ull*)&xv)[0], xb = ((ull*)&xv)[1];
                        fma2(acc[p][0], xa, m0a); fma2(acc[p][0], xb, m0b);
                        fma2(acc[p][1], xa, m1a); fma2(acc[p][1], xb, m1b);
                        fma2(acc[p][2], xa, m2a); fma2(acc[p][2], xb, m2b);
                        fma2(acc[p][3], xa, m3a); fma2(acc[p][3], xb, m3b);
                    }
                    gr++; if (gr == 50) gr = 0;
                }
            }
            __syncthreads();   // all reads of sX complete

            if (act) {
                #pragma unroll
                for (int p = 0; p < NP; p++) {
                    float2 v0 = *(float2*)&acc[p][0];
                    float2 v1 = *(float2*)&acc[p][1];
                    float2 v2 = *(float2*)&acc[p][2];
                    float2 v3 = *(float2*)&acc[p][3];
                    float4 res;
                    res.x = v0.x + v0.y; res.y = v1.x + v1.y;
                    res.z = v2.x + v2.y; res.w = v3.x + v3.y;
                    *(float4*)(sX + (pg * NP + p) * D + 4 * ct) = res;
                }
            }
            __syncthreads();

            // ---- inverse L2 norms ----
            #pragma unroll
            for (int q = 0; q < 5; q++) {
                int pair = warp * 5 + q;
                if (pair < apairs) {
                    const float4* v4 = (const float4*)(sX + pair * D);
                    float4 a = v4[lane];
                    float ss = a.x * a.x + a.y * a.y + a.z * a.z + a.w * a.w;
                    if (lane < 18) {
                        float4 b = v4[lane + 32];
                        ss += b.x * b.x + b.y * b.y + b.z * b.z + b.w * b.w;
                    }
                    #pragma unroll
                    for (int o = 16; o; o >>= 1) ss += __shfl_xor_sync(0xffffffffu, ss, o);
                    if (lane == 0) sNI[pair] = rsqrtf(fmaxf(ss, 1e-12f));
                }
            }
            __syncthreads();

            // ---- scores ----
            {
                float ri = *sRi;
                const float4* r4 = (const float4*)sR;
                for (int task = warp; task < 2 * cnt; task += 16) {
                    int it = task >> 1, s = task & 1;
                    int hp = it * 4 + 2 * s, tp = hp + 1;
                    float ih = sNI[hp], iT = sNI[tp];
                    const float4* vh = (const float4*)(sX + hp * D);
                    const float4* vt = (const float4*)(sX + tp * D);
                    float4 h4 = vh[lane], t4 = vt[lane], rr = r4[lane];
                    float sc = fabsf(h4.x * ih + rr.x * ri - t4.x * iT)
                             + fabsf(h4.y * ih + rr.y * ri - t4.y * iT)
                             + fabsf(h4.z * ih + rr.z * ri - t4.z * iT)
                             + fabsf(h4.w * ih + rr.w * ri - t4.w * iT);
                    if (lane < 18) {
                        float4 h2 = vh[lane + 32], t2 = vt[lane + 32], r2 = r4[lane + 32];
                        sc += fabsf(h2.x * ih + r2.x * ri - t2.x * iT)
                            + fabsf(h2.y * ih + r2.y * ri - t2.y * iT)
                            + fabsf(h2.z * ih + r2.z * ri - t2.z * iT)
                            + fabsf(h2.w * ih + r2.w * ri - t2.w * iT);
                    }
                    #pragma unroll
                    for (int o = 16; o; o >>= 1) sc += __shfl_xor_sync(0xffffffffu, sc, o);
                    if (lane == 0) sSc[task] = sc;
                }
            }
            __syncthreads();

            if (t == 0) {
                for (int it = 0; it < cnt; it++) {
                    float v = sSc[2 * it] - sSc[2 * it + 1] + MARGIN;
                    if (v > 0.f) csum += (double)v;
                }
            }
        }

        if (t == 0) g_part[r] = csum;
    }
}

// ---------------- final deterministic tree reduce ----------------
__global__ void k_final(float* out) {
    __shared__ double s[512];
    int t = threadIdx.x;
    double v = 0.0;
    if (t < 500) v = g_part[t] + g_part[t + 500];
    s[t] = v;
    __syncthreads();
    for (int o = 256; o; o >>= 1) {
        if (t < o) s[t] += s[t + o];
        __syncthreads();
    }
    if (t == 0) out[0] = (float)(s[0] / (double)BATCH);
}

extern "C" void kernel_launch(void* const* d_in, const int* in_sizes, int n_in,
                              void* d_out, int out_size) {
    const int*   pos_h    = (const int*)d_in[0];
    const int*   pos_t    = (const int*)d_in[1];
    const int*   pos_r    = (const int*)d_in[2];
    const int*   neg_h    = (const int*)d_in[3];
    const int*   neg_t    = (const int*)d_in[4];
    const float* ent      = (const float*)d_in[5];
    const float* rel      = (const float*)d_in[6];
    const float* transfer = (const float*)d_in[7];
    float* out = (float*)d_out;

    cudaFuncSetAttribute(k_main, cudaFuncAttributeMaxDynamicSharedMemorySize, SMEM_BYTES);

    k_prep<<<1, 1024>>>(pos_r);
    k_main<<<GRID_MAIN, THREADS, SMEM_BYTES>>>(pos_h, pos_t, neg_h, neg_t,
                                               ent, rel, transfer);
    k_final<<<1, 512>>>(out);
}